// round 3
// baseline (speedup 1.0000x reference)
#include <cuda_runtime.h>
#include <math.h>

// ---------------------------------------------------------------------------
// QuantumNATExtendedQML — R2: f32x2 packed-FMA convs, LDS.128 conv2 tiles,
// two oc-groups per block (tile loaded once), channel-last layouts.
// ---------------------------------------------------------------------------

#define NB 128
typedef unsigned long long ull;

// persistent device scratch (no cudaMalloc allowed)
__device__ double g_p1[896 * 16];                        // conv1 per-block partials
__device__ double g_p2[1792 * 8];                        // conv2 per-block partials
__device__ __align__(16) float g_a1[8], g_c1[8];         // bn1 affine
__device__ __align__(16) float g_a2[4], g_c2[4];         // bn2 affine
__device__ __align__(16) float g_h1[NB * 112 * 112 * 8]; // pooled conv1, ch-last
__device__ __align__(16) float g_y2[NB * 112 * 112 * 4]; // raw conv2, ch-last
__device__ __align__(16) float g_feat[NB * 4];

// ---- f32x2 helpers --------------------------------------------------------
__device__ __forceinline__ ull pk(float lo, float hi) {
    ull r;
    asm("mov.b64 %0, {%1, %2};" : "=l"(r) : "f"(lo), "f"(hi));
    return r;
}
__device__ __forceinline__ void upk(ull v, float& lo, float& hi) {
    asm("mov.b64 {%0, %1}, %2;" : "=f"(lo), "=f"(hi) : "l"(v));
}
__device__ __forceinline__ ull fma2(ull a, ull b, ull c) {
    ull d;
    asm("fma.rn.f32x2 %0, %1, %2, %3;" : "=l"(d) : "l"(a), "l"(b), "l"(c));
    return d;
}
__device__ __forceinline__ ull add2(ull a, ull b) {
    ull d;
    asm("add.rn.f32x2 %0, %1, %2;" : "=l"(d) : "l"(a), "l"(b));
    return d;
}

__device__ __forceinline__ float warp_sum(float v) {
#pragma unroll
    for (int o = 16; o > 0; o >>= 1) v += __shfl_xor_sync(0xffffffffu, v, o);
    return v;
}

// ---------------------------------------------------------------------------
// conv1 stats: grid(7, 128), block 448.
// tid<224: oc group 0 (oc 0..3), col=tid; tid>=224: group 1 (oc 4..7).
// Each thread: column strip of 32 conv rows, packed as row-pairs (r, r+16).
__global__ void __launch_bounds__(448) k_conv1_stats(const float* __restrict__ x,
                                                     const float* __restrict__ w,
                                                     const float* __restrict__ bias) {
    __shared__ float tile[34][226];
    __shared__ double sacc[16];
    const int n = blockIdx.y, h0 = blockIdx.x * 32, tid = threadIdx.x;
    const int grp = tid / 224, c = tid % 224;

    const float* xim = x + (size_t)n * 224 * 224;
    for (int i = tid; i < 34 * 226; i += 448) {
        int r = i / 226, cc = i % 226;
        int hh = h0 - 1 + r, ww = cc - 1;
        float v = 0.f;
        if (hh >= 0 && hh < 224 && ww >= 0 && ww < 224) v = xim[hh * 224 + ww];
        tile[r][cc] = v;
    }
    if (tid < 16) sacc[tid] = 0.0;

    // this group's 4 ocs: packed (w,w) weights + packed bias
    ull wpk[36], bpk[4];
    const float* wg = w + grp * 36;
#pragma unroll
    for (int k = 0; k < 36; k++) { float t = wg[k]; wpk[k] = pk(t, t); }
#pragma unroll
    for (int j = 0; j < 4; j++) { float t = bias[grp * 4 + j]; bpk[j] = pk(t, t); }
    __syncthreads();

    ull s[4], q[4];
#pragma unroll
    for (int j = 0; j < 4; j++) { s[j] = 0ULL; q[j] = 0ULL; }

    ull w0[3], w1[3];
#pragma unroll
    for (int k = 0; k < 3; k++) {
        w0[k] = pk(tile[0][c + k], tile[16][c + k]);
        w1[k] = pk(tile[1][c + k], tile[17][c + k]);
    }
#pragma unroll 4
    for (int r = 0; r < 16; r++) {
        ull w2v[3];
#pragma unroll
        for (int k = 0; k < 3; k++)
            w2v[k] = pk(tile[r + 2][c + k], tile[r + 18][c + k]);
#pragma unroll
        for (int j = 0; j < 4; j++) {
            ull y = bpk[j];
            y = fma2(wpk[j * 9 + 0], w0[0], y);
            y = fma2(wpk[j * 9 + 1], w0[1], y);
            y = fma2(wpk[j * 9 + 2], w0[2], y);
            y = fma2(wpk[j * 9 + 3], w1[0], y);
            y = fma2(wpk[j * 9 + 4], w1[1], y);
            y = fma2(wpk[j * 9 + 5], w1[2], y);
            y = fma2(wpk[j * 9 + 6], w2v[0], y);
            y = fma2(wpk[j * 9 + 7], w2v[1], y);
            y = fma2(wpk[j * 9 + 8], w2v[2], y);
            s[j] = add2(s[j], y);
            q[j] = fma2(y, y, q[j]);
        }
#pragma unroll
        for (int k = 0; k < 3; k++) { w0[k] = w1[k]; w1[k] = w2v[k]; }
    }

#pragma unroll
    for (int j = 0; j < 4; j++) {
        float slo, shi, qlo, qhi;
        upk(s[j], slo, shi);
        upk(q[j], qlo, qhi);
        float ws = warp_sum(slo + shi);
        float wq = warp_sum(qlo + qhi);
        if ((tid & 31) == 0) {
            atomicAdd(&sacc[grp * 4 + j], (double)ws);
            atomicAdd(&sacc[8 + grp * 4 + j], (double)wq);
        }
    }
    __syncthreads();
    if (tid < 16) g_p1[(size_t)(blockIdx.y * 7 + blockIdx.x) * 16 + tid] = sacc[tid];
}

__global__ void k_fin1(const float* __restrict__ g, const float* __restrict__ b) {
    __shared__ double red[128];
    const int tid = threadIdx.x;
    const int st = tid & 15, ch = tid >> 4;
    double s = 0.0;
    for (int i = ch; i < 896; i += 8) s += g_p1[i * 16 + st];
    red[tid] = s;
    __syncthreads();
    if (tid < 16) {
        double t = red[tid];
#pragma unroll
        for (int j = 1; j < 8; j++) t += red[j * 16 + tid];
        red[tid] = t;
    }
    __syncthreads();
    if (tid < 8) {
        double N = 128.0 * 224.0 * 224.0;
        double mu = red[tid] / N;
        double var = red[8 + tid] / N - mu * mu;
        double a = (double)g[tid] * rsqrt(var + 1e-5);
        g_a1[tid] = (float)a;
        g_c1[tid] = (float)((double)b[tid] - mu * a);
    }
}

// ---------------------------------------------------------------------------
// conv1 main: conv+bn+relu+pool -> h1 (channel-last).
// grid(8, 128), block 224.  tid<112: oc group 0, col=tid; else group 1.
// Each thread: 14 pooled rows; pool-window columns (dx=0,1) packed in f32x2.
__global__ void __launch_bounds__(224) k_conv1_main(const float* __restrict__ x,
                                                    const float* __restrict__ w,
                                                    const float* __restrict__ bias) {
    __shared__ float tile[30][226];
    const int n = blockIdx.y, tid = threadIdx.x;
    const int grp = tid / 112, col = tid % 112;
    const int h0in = blockIdx.x * 28 - 1;

    const float* xim = x + (size_t)n * 224 * 224;
    for (int i = tid; i < 30 * 226; i += 224) {
        int r = i / 226, cc = i % 226;
        int hh = h0in + r, ww = cc - 1;
        float v = 0.f;
        if (hh >= 0 && hh < 224 && ww >= 0 && ww < 224) v = xim[hh * 224 + ww];
        tile[r][cc] = v;
    }

    // group weights with BN folded, packed (w,w)
    ull wpk[36], bpk[4];
#pragma unroll
    for (int j = 0; j < 4; j++) {
        int oc = grp * 4 + j;
        float a = g_a1[oc], cc = g_c1[oc];
#pragma unroll
        for (int k = 0; k < 9; k++) {
            float t = w[oc * 9 + k] * a;
            wpk[j * 9 + k] = pk(t, t);
        }
        float br = fmaf(bias[oc], a, cc);
        bpk[j] = pk(br, br);
    }
    __syncthreads();

    const int c0 = 2 * col;
    float v[4][4];
#pragma unroll
    for (int rr = 0; rr < 2; rr++)
#pragma unroll
        for (int i = 0; i < 4; i++) v[rr][i] = tile[rr][c0 + i];
    ull pv[4][3];
#pragma unroll
    for (int rr = 0; rr < 2; rr++)
#pragma unroll
        for (int k = 0; k < 3; k++) pv[rr][k] = pk(v[rr][k], v[rr][k + 1]);

    float* outp = &g_h1[(((size_t)n * 112 + blockIdx.x * 14) * 112 + col) * 8 + grp * 4];

#pragma unroll 2
    for (int pr = 0; pr < 14; pr++) {
#pragma unroll
        for (int i = 0; i < 4; i++) {
            v[2][i] = tile[2 * pr + 2][c0 + i];
            v[3][i] = tile[2 * pr + 3][c0 + i];
        }
#pragma unroll
        for (int k = 0; k < 3; k++) {
            pv[2][k] = pk(v[2][k], v[2][k + 1]);
            pv[3][k] = pk(v[3][k], v[3][k + 1]);
        }
        float o[4];
#pragma unroll
        for (int j = 0; j < 4; j++) {
            ull z0 = bpk[j], z1 = bpk[j];
            z0 = fma2(wpk[j * 9 + 0], pv[0][0], z0);
            z0 = fma2(wpk[j * 9 + 1], pv[0][1], z0);
            z0 = fma2(wpk[j * 9 + 2], pv[0][2], z0);
            z0 = fma2(wpk[j * 9 + 3], pv[1][0], z0);
            z0 = fma2(wpk[j * 9 + 4], pv[1][1], z0);
            z0 = fma2(wpk[j * 9 + 5], pv[1][2], z0);
            z0 = fma2(wpk[j * 9 + 6], pv[2][0], z0);
            z0 = fma2(wpk[j * 9 + 7], pv[2][1], z0);
            z0 = fma2(wpk[j * 9 + 8], pv[2][2], z0);
            z1 = fma2(wpk[j * 9 + 0], pv[1][0], z1);
            z1 = fma2(wpk[j * 9 + 1], pv[1][1], z1);
            z1 = fma2(wpk[j * 9 + 2], pv[1][2], z1);
            z1 = fma2(wpk[j * 9 + 3], pv[2][0], z1);
            z1 = fma2(wpk[j * 9 + 4], pv[2][1], z1);
            z1 = fma2(wpk[j * 9 + 5], pv[2][2], z1);
            z1 = fma2(wpk[j * 9 + 6], pv[3][0], z1);
            z1 = fma2(wpk[j * 9 + 7], pv[3][1], z1);
            z1 = fma2(wpk[j * 9 + 8], pv[3][2], z1);
            float a0, a1, b0, b1;
            upk(z0, a0, a1);
            upk(z1, b0, b1);
            o[j] = fmaxf(fmaxf(fmaxf(a0, a1), fmaxf(b0, b1)), 0.f);
        }
        *(float4*)outp = make_float4(o[0], o[1], o[2], o[3]);
        outp += 112 * 8;
#pragma unroll
        for (int i = 0; i < 4; i++) { v[0][i] = v[2][i]; v[1][i] = v[3][i]; }
#pragma unroll
        for (int k = 0; k < 3; k++) { pv[0][k] = pv[2][k]; pv[1][k] = pv[3][k]; }
    }
}

// ---------------------------------------------------------------------------
// conv2 (oc 0..3): raw y2 (ch-last) + per-block partial stats.
// grid(14, 128), block 224.  Thread: 1 row x 4 CONTIGUOUS pixels.
// Tile: padded per-channel planes -> v via 2x LDS.128; pixel pairs in f32x2.
__global__ void __launch_bounds__(224) k_conv2(const float* __restrict__ w2,
                                               const float* __restrict__ b2) {
    __shared__ float tile[8][10][120];
    __shared__ ulonglong2 wsp[72][2];   // [ic*9+k][0]=(oc0,oc1) [1]=(oc2,oc3), packed (w,w)
    __shared__ ull bpk[4];
    __shared__ double sacc[8];
    const int n = blockIdx.y, h0 = blockIdx.x * 8, tid = threadIdx.x;

    for (int i = tid; i < 10 * 114; i += 224) {
        int r = i / 114, c = i % 114;
        int hh = h0 - 1 + r, ww = c - 1;
        float4 p0 = make_float4(0.f, 0.f, 0.f, 0.f), p1 = p0;
        if (hh >= 0 && hh < 112 && ww >= 0 && ww < 112) {
            const float4* hp = (const float4*)&g_h1[(((size_t)n * 112 + hh) * 112 + ww) * 8];
            p0 = hp[0]; p1 = hp[1];
        }
        tile[0][r][c] = p0.x; tile[1][r][c] = p0.y; tile[2][r][c] = p0.z; tile[3][r][c] = p0.w;
        tile[4][r][c] = p1.x; tile[5][r][c] = p1.y; tile[6][r][c] = p1.z; tile[7][r][c] = p1.w;
    }
    if (tid < 72) {
        float a = w2[tid], b = w2[72 + tid], c = w2[144 + tid], d = w2[216 + tid];
        wsp[tid][0] = make_ulonglong2(pk(a, a), pk(b, b));
        wsp[tid][1] = make_ulonglong2(pk(c, c), pk(d, d));
    }
    if (tid < 4) { float t = b2[tid]; bpk[tid] = pk(t, t); }
    if (tid < 8) sacc[tid] = 0.0;
    __syncthreads();

    const int r = tid / 28, g = tid % 28;
    ull accA[4], accB[4];  // pixels (0,1) and (2,3)
#pragma unroll
    for (int j = 0; j < 4; j++) { accA[j] = bpk[j]; accB[j] = bpk[j]; }

#pragma unroll 1
    for (int ic = 0; ic < 8; ic++) {
#pragma unroll
        for (int kh = 0; kh < 3; kh++) {
            const float4 va = *(const float4*)&tile[ic][r + kh][4 * g];
            const float4 vb = *(const float4*)&tile[ic][r + kh][4 * g + 4];
            ull pv[5];
            pv[0] = pk(va.x, va.y);
            pv[1] = pk(va.y, va.z);
            pv[2] = pk(va.z, va.w);
            pv[3] = pk(va.w, vb.x);
            pv[4] = pk(vb.x, vb.y);
#pragma unroll
            for (int kw = 0; kw < 3; kw++) {
                ulonglong2 w01 = wsp[ic * 9 + kh * 3 + kw][0];
                ulonglong2 w23 = wsp[ic * 9 + kh * 3 + kw][1];
                ull pa = pv[kw], pb = pv[kw + 2];
                accA[0] = fma2(w01.x, pa, accA[0]);
                accA[1] = fma2(w01.y, pa, accA[1]);
                accA[2] = fma2(w23.x, pa, accA[2]);
                accA[3] = fma2(w23.y, pa, accA[3]);
                accB[0] = fma2(w01.x, pb, accB[0]);
                accB[1] = fma2(w01.y, pb, accB[1]);
                accB[2] = fma2(w23.x, pb, accB[2]);
                accB[3] = fma2(w23.y, pb, accB[3]);
            }
        }
    }

    float y[4][4];
#pragma unroll
    for (int j = 0; j < 4; j++) {
        upk(accA[j], y[j][0], y[j][1]);
        upk(accB[j], y[j][2], y[j][3]);
    }
    const int hh = h0 + r;
    float* base = &g_y2[(((size_t)n * 112 + hh) * 112 + 4 * g) * 4];
#pragma unroll
    for (int p = 0; p < 4; p++)
        *(float4*)(base + p * 4) = make_float4(y[0][p], y[1][p], y[2][p], y[3][p]);

#pragma unroll
    for (int j = 0; j < 4; j++) {
        float s = (y[j][0] + y[j][1]) + (y[j][2] + y[j][3]);
        float q = fmaf(y[j][0], y[j][0], fmaf(y[j][1], y[j][1],
                  fmaf(y[j][2], y[j][2], y[j][3] * y[j][3])));
        float ws = warp_sum(s);
        float wq = warp_sum(q);
        if ((tid & 31) == 0) {
            atomicAdd(&sacc[j], (double)ws);
            atomicAdd(&sacc[4 + j], (double)wq);
        }
    }
    __syncthreads();
    if (tid < 8) g_p2[(size_t)(blockIdx.y * 14 + blockIdx.x) * 8 + tid] = sacc[tid];
}

__global__ void k_fin2(const float* __restrict__ g, const float* __restrict__ b) {
    __shared__ double red[128];
    const int tid = threadIdx.x;
    const int st = tid & 7, ch = tid >> 3;
    double s = 0.0;
    for (int i = ch; i < 1792; i += 16) s += g_p2[i * 8 + st];
    red[tid] = s;
    __syncthreads();
    if (tid < 8) {
        double t = red[tid];
#pragma unroll
        for (int j = 1; j < 16; j++) t += red[j * 8 + tid];
        red[tid] = t;
    }
    __syncthreads();
    if (tid < 4) {
        double N = 128.0 * 112.0 * 112.0;
        double mu = red[tid] / N;
        double var = red[4 + tid] / N - mu * mu;
        double a = (double)g[tid] * rsqrt(var + 1e-5);
        g_a2[tid] = (float)a;
        g_c2[tid] = (float)((double)b[tid] - mu * a);
    }
}

// ---------------------------------------------------------------------------
// bn + relu + maxpool + spatial mean on stored y2 (channel-last). grid(128).
__global__ void k_pool_mean() {
    const int n = blockIdx.x, tid = threadIdx.x;
    const float4 av = *(const float4*)g_a2;
    const float4 cv = *(const float4*)g_c2;
    const float* base = &g_y2[(size_t)n * 112 * 112 * 4];
    float4 acc = make_float4(0.f, 0.f, 0.f, 0.f);

    for (int p = tid; p < 56 * 56; p += 256) {
        int pr = p / 56, pw = p % 56;
        const float4* q0 = (const float4*)(base + ((2 * pr) * 112 + 2 * pw) * 4);
        const float4* q1 = (const float4*)(base + ((2 * pr + 1) * 112 + 2 * pw) * 4);
        float4 y00 = q0[0], y01 = q0[1], y10 = q1[0], y11 = q1[1];
        float4 m;
        m.x = fmaxf(fmaxf(fmaf(y00.x, av.x, cv.x), fmaf(y01.x, av.x, cv.x)),
                    fmaxf(fmaf(y10.x, av.x, cv.x), fmaf(y11.x, av.x, cv.x)));
        m.y = fmaxf(fmaxf(fmaf(y00.y, av.y, cv.y), fmaf(y01.y, av.y, cv.y)),
                    fmaxf(fmaf(y10.y, av.y, cv.y), fmaf(y11.y, av.y, cv.y)));
        m.z = fmaxf(fmaxf(fmaf(y00.z, av.z, cv.z), fmaf(y01.z, av.z, cv.z)),
                    fmaxf(fmaf(y10.z, av.z, cv.z), fmaf(y11.z, av.z, cv.z)));
        m.w = fmaxf(fmaxf(fmaf(y00.w, av.w, cv.w), fmaf(y01.w, av.w, cv.w)),
                    fmaxf(fmaf(y10.w, av.w, cv.w), fmaf(y11.w, av.w, cv.w)));
        acc.x += fmaxf(m.x, 0.f);
        acc.y += fmaxf(m.y, 0.f);
        acc.z += fmaxf(m.z, 0.f);
        acc.w += fmaxf(m.w, 0.f);
    }
    __shared__ float4 sm[8];
    acc.x = warp_sum(acc.x); acc.y = warp_sum(acc.y);
    acc.z = warp_sum(acc.z); acc.w = warp_sum(acc.w);
    if ((tid & 31) == 0) sm[tid >> 5] = acc;
    __syncthreads();
    if (tid == 0) {
        float4 t = make_float4(0.f, 0.f, 0.f, 0.f);
#pragma unroll
        for (int i = 0; i < 8; i++) {
            t.x += sm[i].x; t.y += sm[i].y; t.z += sm[i].z; t.w += sm[i].w;
        }
        *(float4*)&g_feat[n * 4] =
            make_float4(t.x / 3136.f, t.y / 3136.f, t.z / 3136.f, t.w / 3136.f);
    }
}

// ---------------------------------------------------------------------------
// Quantum circuit (unchanged, passing since R0).
template <int Q>
__device__ __forceinline__ void ry_gate(float2* st, float t) {
    float s, c;
    sincosf(0.5f * t, &s, &c);
    const int m = 8 >> Q;
#pragma unroll
    for (int i = 0; i < 16; i++)
        if (!(i & m)) {
            float2 a0 = st[i], a1 = st[i | m];
            st[i]     = make_float2(c * a0.x - s * a1.x, c * a0.y - s * a1.y);
            st[i | m] = make_float2(s * a0.x + c * a1.x, s * a0.y + c * a1.y);
        }
}
template <int Q>
__device__ __forceinline__ void rz_gate(float2* st, float t) {
    float s, c;
    sincosf(0.5f * t, &s, &c);
    const int m = 8 >> Q;
#pragma unroll
    for (int i = 0; i < 16; i++)
        if (!(i & m)) {
            float2 a0 = st[i], a1 = st[i | m];
            st[i]     = make_float2(c * a0.x + s * a0.y, c * a0.y - s * a0.x);
            st[i | m] = make_float2(c * a1.x - s * a1.y, c * a1.y + s * a1.x);
        }
}
template <int Q>
__device__ __forceinline__ void rx_gate(float2* st, float t) {
    float s, c;
    sincosf(0.5f * t, &s, &c);
    const int m = 8 >> Q;
#pragma unroll
    for (int i = 0; i < 16; i++)
        if (!(i & m)) {
            float2 a0 = st[i], a1 = st[i | m];
            st[i]     = make_float2(c * a0.x + s * a1.y, c * a0.y - s * a1.x);
            st[i | m] = make_float2(c * a1.x + s * a0.y, c * a1.y - s * a0.x);
        }
}
template <int C, int T>
__device__ __forceinline__ void cnot_gate(float2* st) {
    const int mc = 8 >> C, mt = 8 >> T;
#pragma unroll
    for (int i = 0; i < 16; i++)
        if ((i & mc) && !(i & mt)) {
            float2 tmp = st[i];
            st[i] = st[i | mt];
            st[i | mt] = tmp;
        }
}

__global__ void k_final(const float* __restrict__ theta, const float* __restrict__ rho,
                        const float* __restrict__ ng, const float* __restrict__ nb,
                        float* __restrict__ out) {
    const int tid = threadIdx.x;  // 128 threads, one per batch element
    float f[4];
#pragma unroll
    for (int j = 0; j < 4; j++) f[j] = g_feat[tid * 4 + j];

    __shared__ double ssum, ssq;
    if (tid == 0) { ssum = 0.0; ssq = 0.0; }
    __syncthreads();
    float lf = f[0] + f[1] + f[2] + f[3];
    float lq = f[0] * f[0] + f[1] * f[1] + f[2] * f[2] + f[3] * f[3];
    float ws = warp_sum(lf), wq = warp_sum(lq);
    if ((tid & 31) == 0) { atomicAdd(&ssum, (double)ws); atomicAdd(&ssq, (double)wq); }
    __syncthreads();
    double mean = ssum / 512.0;
    double var1 = (ssq - 512.0 * mean * mean) / 511.0;
    if (var1 < 0.0) var1 = 0.0;
    float scale = (float)(3.14159265358979323846 / (sqrt(var1) + 1e-6));
    float sc[4];
#pragma unroll
    for (int j = 0; j < 4; j++) sc[j] = (float)((double)f[j] - mean) * scale;

    float2 st[16];
#pragma unroll
    for (int i = 0; i < 16; i++) st[i] = make_float2(0.f, 0.f);
    st[0].x = 1.f;

    ry_gate<0>(st, sc[0]); ry_gate<1>(st, sc[1]); ry_gate<2>(st, sc[2]); ry_gate<3>(st, sc[3]);

    ry_gate<0>(st, theta[0]);  rz_gate<0>(st, theta[1]);  rx_gate<0>(st, theta[2]);
    ry_gate<1>(st, theta[3]);  rz_gate<1>(st, theta[4]);  rx_gate<1>(st, theta[5]);
    ry_gate<2>(st, theta[6]);  rz_gate<2>(st, theta[7]);  rx_gate<2>(st, theta[8]);
    ry_gate<3>(st, theta[9]);  rz_gate<3>(st, theta[10]); rx_gate<3>(st, theta[11]);

    cnot_gate<0, 1>(st); cnot_gate<1, 2>(st); cnot_gate<2, 3>(st);

    ry_gate<0>(st, rho[0]);  rz_gate<0>(st, rho[1]);  rx_gate<0>(st, rho[2]);
    ry_gate<1>(st, rho[3]);  rz_gate<1>(st, rho[4]);  rx_gate<1>(st, rho[5]);
    ry_gate<2>(st, rho[6]);  rz_gate<2>(st, rho[7]);  rx_gate<2>(st, rho[8]);
    ry_gate<3>(st, rho[9]);  rz_gate<3>(st, rho[10]); rx_gate<3>(st, rho[11]);

    cnot_gate<1, 0>(st); cnot_gate<2, 1>(st); cnot_gate<3, 2>(st);

    float pr[16];
#pragma unroll
    for (int i = 0; i < 16; i++) pr[i] = st[i].x * st[i].x + st[i].y * st[i].y;

    float e[4];
#pragma unroll
    for (int q = 0; q < 4; q++) {
        const int m = 8 >> q;
        float acc = 0.f;
#pragma unroll
        for (int i = 0; i < 16; i++) acc += (i & m) ? -pr[i] : pr[i];
        e[q] = acc;
    }

    __shared__ double s1, s2;
#pragma unroll
    for (int j = 0; j < 4; j++) {
        if (tid == 0) { s1 = 0.0; s2 = 0.0; }
        __syncthreads();
        float v = e[j];
        float w1 = warp_sum(v), w2 = warp_sum(v * v);
        if ((tid & 31) == 0) { atomicAdd(&s1, (double)w1); atomicAdd(&s2, (double)w2); }
        __syncthreads();
        double mu = s1 / 128.0;
        double vv = s2 / 128.0 - mu * mu;
        out[tid * 4 + j] =
            (float)(((double)v - mu) * rsqrt(vv + 1e-5) * (double)ng[j] + (double)nb[j]);
        __syncthreads();
    }
}

// ---------------------------------------------------------------------------
extern "C" void kernel_launch(void* const* d_in, const int* in_sizes, int n_in,
                              void* d_out, int out_size) {
    const float* x     = (const float*)d_in[0];
    const float* w1    = (const float*)d_in[1];
    const float* b1    = (const float*)d_in[2];
    const float* bn1g  = (const float*)d_in[3];
    const float* bn1b  = (const float*)d_in[4];
    const float* w2    = (const float*)d_in[5];
    const float* b2    = (const float*)d_in[6];
    const float* bn2g  = (const float*)d_in[7];
    const float* bn2b  = (const float*)d_in[8];
    const float* theta = (const float*)d_in[9];
    const float* rho   = (const float*)d_in[10];
    const float* ng    = (const float*)d_in[11];
    const float* nbp   = (const float*)d_in[12];
    float* out = (float*)d_out;

    k_conv1_stats<<<dim3(7, NB), 448>>>(x, w1, b1);
    k_fin1<<<1, 128>>>(bn1g, bn1b);
    k_conv1_main<<<dim3(8, NB), 224>>>(x, w1, b1);
    k_conv2<<<dim3(14, NB), 224>>>(w2, b2);
    k_fin2<<<1, 128>>>(bn2g, bn2b);
    k_pool_mean<<<128, 256>>>();
    k_final<<<1, 128>>>(theta, rho, ng, nbp, out);
}

// round 4
// speedup vs baseline: 1.3479x; 1.3479x over previous
#include <cuda_runtime.h>
#include <math.h>

// ---------------------------------------------------------------------------
// QuantumNATExtendedQML — R3: fused conv1 (stats + raw-max/min pooling),
// conv2 applies bn1 affine on tile load (sign-aware select), in-block pooling
// of raw conv2 output (y2 never materialized). All scalar FFMA.
// ---------------------------------------------------------------------------

#define NB 128

// persistent device scratch (no cudaMalloc allowed)
__device__ double g_p1[896 * 16];                          // conv1 per-block partials
__device__ double g_p2[1792 * 8];                          // conv2 per-block partials
__device__ __align__(16) float g_a1[8], g_c1[8];           // bn1 affine
__device__ __align__(16) float g_a2[4], g_c2[4];           // bn2 affine
__device__ __align__(16) float g_h1max[NB * 112 * 112 * 8];// pooled raw conv1 max, ch-last
__device__ __align__(16) float g_h1min[NB * 112 * 112 * 8];// pooled raw conv1 min, ch-last
__device__ __align__(16) float g_pmax[NB * 56 * 56 * 4];   // pooled raw conv2 max, ch-last
__device__ __align__(16) float g_pmin[NB * 56 * 56 * 4];   // pooled raw conv2 min, ch-last
__device__ __align__(16) float g_feat[NB * 4];

__device__ __forceinline__ float warp_sum(float v) {
#pragma unroll
    for (int o = 16; o > 0; o >>= 1) v += __shfl_xor_sync(0xffffffffu, v, o);
    return v;
}

// ---------------------------------------------------------------------------
// Fused conv1: raw conv output y -> (sum, sumsq) partials + 2x2 pooled
// raw max/min (ch-last) in one pass over x.
// grid(7, 128), block 256.  grp = tid/128 handles oc group grp*4..grp*4+3
// (warp-aligned).  pc = tid%128 (< 112 active) owns pooled column pc
// (conv cols 2pc, 2pc+1), strip of 32 conv rows -> 16 pooled rows.
__global__ void __launch_bounds__(256) k_conv1(const float* __restrict__ x,
                                               const float* __restrict__ w,
                                               const float* __restrict__ bias) {
    __shared__ float tile[34][226];
    __shared__ double sacc[16];
    const int n = blockIdx.y, h0 = blockIdx.x * 32, tid = threadIdx.x;
    const int grp = tid >> 7, pc = tid & 127;

    const float* xim = x + (size_t)n * 224 * 224;
    for (int i = tid; i < 34 * 226; i += 256) {
        int r = i / 226, c = i % 226;
        int hh = h0 - 1 + r, ww = c - 1;
        float v = 0.f;
        if (hh >= 0 && hh < 224 && ww >= 0 && ww < 224) v = xim[hh * 224 + ww];
        tile[r][c] = v;
    }
    if (tid < 16) sacc[tid] = 0.0;

    float wr[36], br[4];
#pragma unroll
    for (int j = 0; j < 4; j++) {
        int oc = grp * 4 + j;
#pragma unroll
        for (int k = 0; k < 9; k++) wr[j * 9 + k] = w[oc * 9 + k];
        br[j] = bias[oc];
    }
    __syncthreads();

    float s[4] = {0.f, 0.f, 0.f, 0.f}, q[4] = {0.f, 0.f, 0.f, 0.f};

    if (pc < 112) {
        const int c0 = 2 * pc;
        float t0[4], t1[4];
#pragma unroll
        for (int i = 0; i < 4; i++) { t0[i] = tile[0][c0 + i]; t1[i] = tile[1][c0 + i]; }
        float mx[4], mn[4];

        float* pmax = &g_h1max[(((size_t)n * 112 + blockIdx.x * 16) * 112 + pc) * 8 + grp * 4];
        float* pmin = &g_h1min[(((size_t)n * 112 + blockIdx.x * 16) * 112 + pc) * 8 + grp * 4];

#pragma unroll 2
        for (int r = 0; r < 32; r++) {
            float t2[4];
#pragma unroll
            for (int i = 0; i < 4; i++) t2[i] = tile[r + 2][c0 + i];
#pragma unroll
            for (int j = 0; j < 4; j++) {
                const float* wk = &wr[j * 9];
                float z0 = br[j], z1 = br[j];
                z0 = fmaf(wk[0], t0[0], z0); z1 = fmaf(wk[0], t0[1], z1);
                z0 = fmaf(wk[1], t0[1], z0); z1 = fmaf(wk[1], t0[2], z1);
                z0 = fmaf(wk[2], t0[2], z0); z1 = fmaf(wk[2], t0[3], z1);
                z0 = fmaf(wk[3], t1[0], z0); z1 = fmaf(wk[3], t1[1], z1);
                z0 = fmaf(wk[4], t1[1], z0); z1 = fmaf(wk[4], t1[2], z1);
                z0 = fmaf(wk[5], t1[2], z0); z1 = fmaf(wk[5], t1[3], z1);
                z0 = fmaf(wk[6], t2[0], z0); z1 = fmaf(wk[6], t2[1], z1);
                z0 = fmaf(wk[7], t2[1], z0); z1 = fmaf(wk[7], t2[2], z1);
                z0 = fmaf(wk[8], t2[2], z0); z1 = fmaf(wk[8], t2[3], z1);
                s[j] += z0 + z1;
                q[j] = fmaf(z0, z0, fmaf(z1, z1, q[j]));
                float hi = fmaxf(z0, z1), lo = fminf(z0, z1);
                if (r & 1) {
                    mx[j] = fmaxf(mx[j], hi);
                    mn[j] = fminf(mn[j], lo);
                } else {
                    mx[j] = hi;
                    mn[j] = lo;
                }
            }
            if (r & 1) {
                *(float4*)pmax = make_float4(mx[0], mx[1], mx[2], mx[3]);
                *(float4*)pmin = make_float4(mn[0], mn[1], mn[2], mn[3]);
                pmax += 112 * 8;
                pmin += 112 * 8;
            }
#pragma unroll
            for (int i = 0; i < 4; i++) { t0[i] = t1[i]; t1[i] = t2[i]; }
        }
    }

#pragma unroll
    for (int j = 0; j < 4; j++) {
        float ws = warp_sum(s[j]);
        float wq = warp_sum(q[j]);
        if ((tid & 31) == 0) {
            atomicAdd(&sacc[grp * 4 + j], (double)ws);
            atomicAdd(&sacc[8 + grp * 4 + j], (double)wq);
        }
    }
    __syncthreads();
    if (tid < 16) g_p1[(size_t)(blockIdx.y * 7 + blockIdx.x) * 16 + tid] = sacc[tid];
}

__global__ void k_fin1(const float* __restrict__ g, const float* __restrict__ b) {
    __shared__ double red[128];
    const int tid = threadIdx.x;
    const int st = tid & 15, ch = tid >> 4;
    double s = 0.0;
    for (int i = ch; i < 896; i += 8) s += g_p1[i * 16 + st];
    red[tid] = s;
    __syncthreads();
    if (tid < 16) {
        double t = red[tid];
#pragma unroll
        for (int j = 1; j < 8; j++) t += red[j * 16 + tid];
        red[tid] = t;
    }
    __syncthreads();
    if (tid < 8) {
        double N = 128.0 * 224.0 * 224.0;
        double mu = red[tid] / N;
        double var = red[8 + tid] / N - mu * mu;
        double a = (double)g[tid] * rsqrt(var + 1e-5);
        g_a1[tid] = (float)a;
        g_c1[tid] = (float)((double)b[tid] - mu * a);
    }
}

// ---------------------------------------------------------------------------
// conv2 (oc 0..3): h reconstructed on tile load as relu(a1*sel(max,min)+c1);
// raw y2 kept in registers for bn2 stats; in-block 2x2 pooled raw max/min
// written out (y2 itself never stored).
// grid(14, 128), block 224.  Thread (r, g): row r, 4 contiguous pixels.
__global__ void __launch_bounds__(224) k_conv2(const float* __restrict__ w2,
                                               const float* __restrict__ b2) {
    __shared__ float tile[8][10][120];
    __shared__ float4 wq[72];
    __shared__ float4 ybuf[8][112];
    __shared__ float bsh[4];
    __shared__ double sacc[8];
    const int n = blockIdx.y, h0 = blockIdx.x * 8, tid = threadIdx.x;

    // bn1 affine (broadcast via registers)
    float a1r[8], c1r[8];
#pragma unroll
    for (int ch = 0; ch < 8; ch++) { a1r[ch] = g_a1[ch]; c1r[ch] = g_c1[ch]; }

    for (int i = tid; i < 10 * 114; i += 224) {
        int r = i / 114, c = i % 114;
        int hh = h0 - 1 + r, ww = c - 1;
        float v[8];
        if (hh >= 0 && hh < 112 && ww >= 0 && ww < 112) {
            size_t base = (((size_t)n * 112 + hh) * 112 + ww) * 8;
            const float4* mx = (const float4*)&g_h1max[base];
            const float4* mn = (const float4*)&g_h1min[base];
            float4 x0 = mx[0], x1 = mx[1], n0 = mn[0], n1 = mn[1];
            float raw[8] = {a1r[0] >= 0.f ? x0.x : n0.x, a1r[1] >= 0.f ? x0.y : n0.y,
                            a1r[2] >= 0.f ? x0.z : n0.z, a1r[3] >= 0.f ? x0.w : n0.w,
                            a1r[4] >= 0.f ? x1.x : n1.x, a1r[5] >= 0.f ? x1.y : n1.y,
                            a1r[6] >= 0.f ? x1.z : n1.z, a1r[7] >= 0.f ? x1.w : n1.w};
#pragma unroll
            for (int ch = 0; ch < 8; ch++)
                v[ch] = fmaxf(fmaf(raw[ch], a1r[ch], c1r[ch]), 0.f);
        } else {
#pragma unroll
            for (int ch = 0; ch < 8; ch++) v[ch] = 0.f;
        }
#pragma unroll
        for (int ch = 0; ch < 8; ch++) tile[ch][r][c] = v[ch];
    }
    if (tid < 72)  // w2 layout [16][8][3][3]; pack oc 0..3 per (ic,k)
        wq[tid] = make_float4(w2[tid], w2[72 + tid], w2[144 + tid], w2[216 + tid]);
    if (tid < 4) bsh[tid] = b2[tid];
    if (tid < 8) sacc[tid] = 0.0;
    __syncthreads();

    const int r = tid / 28, g = tid % 28;
    float y[4][4];  // [oc][px]
    {
        float b0 = bsh[0], b1 = bsh[1], b2v = bsh[2], b3 = bsh[3];
#pragma unroll
        for (int p = 0; p < 4; p++) {
            y[0][p] = b0; y[1][p] = b1; y[2][p] = b2v; y[3][p] = b3;
        }
    }

#pragma unroll 1
    for (int ic = 0; ic < 8; ic++) {
#pragma unroll
        for (int kh = 0; kh < 3; kh++) {
            const float4 va = *(const float4*)&tile[ic][r + kh][4 * g];
            const float2 vb = *(const float2*)&tile[ic][r + kh][4 * g + 4];
            float t[6] = {va.x, va.y, va.z, va.w, vb.x, vb.y};
#pragma unroll
            for (int kw = 0; kw < 3; kw++) {
                float4 wv = wq[ic * 9 + kh * 3 + kw];
#pragma unroll
                for (int p = 0; p < 4; p++) {
                    float u = t[p + kw];
                    y[0][p] = fmaf(wv.x, u, y[0][p]);
                    y[1][p] = fmaf(wv.y, u, y[1][p]);
                    y[2][p] = fmaf(wv.z, u, y[2][p]);
                    y[3][p] = fmaf(wv.w, u, y[3][p]);
                }
            }
        }
    }

    // bn2 stats on raw y2
#pragma unroll
    for (int j = 0; j < 4; j++) {
        float s = (y[j][0] + y[j][1]) + (y[j][2] + y[j][3]);
        float qq = fmaf(y[j][0], y[j][0], fmaf(y[j][1], y[j][1],
                   fmaf(y[j][2], y[j][2], y[j][3] * y[j][3])));
        float ws = warp_sum(s);
        float wq = warp_sum(qq);
        if ((tid & 31) == 0) {
            atomicAdd(&sacc[j], (double)ws);
            atomicAdd(&sacc[4 + j], (double)wq);
        }
    }

    // stash y into ybuf for in-block 2x2 pooling
#pragma unroll
    for (int p = 0; p < 4; p++)
        ybuf[r][4 * g + p] = make_float4(y[0][p], y[1][p], y[2][p], y[3][p]);
    __syncthreads();

    // 224 threads = 4 pooled rows x 56 pooled cols
    {
        const int ppr = tid / 56, ppw = tid % 56;
        float4 u0 = ybuf[2 * ppr][2 * ppw];
        float4 u1 = ybuf[2 * ppr][2 * ppw + 1];
        float4 u2 = ybuf[2 * ppr + 1][2 * ppw];
        float4 u3 = ybuf[2 * ppr + 1][2 * ppw + 1];
        float4 mx, mn;
        mx.x = fmaxf(fmaxf(u0.x, u1.x), fmaxf(u2.x, u3.x));
        mx.y = fmaxf(fmaxf(u0.y, u1.y), fmaxf(u2.y, u3.y));
        mx.z = fmaxf(fmaxf(u0.z, u1.z), fmaxf(u2.z, u3.z));
        mx.w = fmaxf(fmaxf(u0.w, u1.w), fmaxf(u2.w, u3.w));
        mn.x = fminf(fminf(u0.x, u1.x), fminf(u2.x, u3.x));
        mn.y = fminf(fminf(u0.y, u1.y), fminf(u2.y, u3.y));
        mn.z = fminf(fminf(u0.z, u1.z), fminf(u2.z, u3.z));
        mn.w = fminf(fminf(u0.w, u1.w), fminf(u2.w, u3.w));
        size_t o = (((size_t)n * 56 + (blockIdx.x * 4 + ppr)) * 56 + ppw) * 4;
        *(float4*)&g_pmax[o] = mx;
        *(float4*)&g_pmin[o] = mn;
    }
    if (tid < 8) g_p2[(size_t)(blockIdx.y * 14 + blockIdx.x) * 8 + tid] = sacc[tid];
}

__global__ void k_fin2(const float* __restrict__ g, const float* __restrict__ b) {
    __shared__ double red[128];
    const int tid = threadIdx.x;
    const int st = tid & 7, ch = tid >> 3;
    double s = 0.0;
    for (int i = ch; i < 1792; i += 16) s += g_p2[i * 8 + st];
    red[tid] = s;
    __syncthreads();
    if (tid < 8) {
        double t = red[tid];
#pragma unroll
        for (int j = 1; j < 16; j++) t += red[j * 8 + tid];
        red[tid] = t;
    }
    __syncthreads();
    if (tid < 4) {
        double N = 128.0 * 112.0 * 112.0;
        double mu = red[tid] / N;
        double var = red[4 + tid] / N - mu * mu;
        double a = (double)g[tid] * rsqrt(var + 1e-5);
        g_a2[tid] = (float)a;
        g_c2[tid] = (float)((double)b[tid] - mu * a);
    }
}

// ---------------------------------------------------------------------------
// feat = mean over 56x56 of relu(a2*sel(pmax,pmin)+c2).  grid(128), block 256.
__global__ void k_pool_mean() {
    const int n = blockIdx.x, tid = threadIdx.x;
    const float4 av = *(const float4*)g_a2;
    const float4 cv = *(const float4*)g_c2;
    const float4* pmax = (const float4*)&g_pmax[(size_t)n * 56 * 56 * 4];
    const float4* pmin = (const float4*)&g_pmin[(size_t)n * 56 * 56 * 4];
    float4 acc = make_float4(0.f, 0.f, 0.f, 0.f);

    for (int p = tid; p < 56 * 56; p += 256) {
        float4 mx = pmax[p], mn = pmin[p];
        float vx = av.x >= 0.f ? mx.x : mn.x;
        float vy = av.y >= 0.f ? mx.y : mn.y;
        float vz = av.z >= 0.f ? mx.z : mn.z;
        float vw = av.w >= 0.f ? mx.w : mn.w;
        acc.x += fmaxf(fmaf(vx, av.x, cv.x), 0.f);
        acc.y += fmaxf(fmaf(vy, av.y, cv.y), 0.f);
        acc.z += fmaxf(fmaf(vz, av.z, cv.z), 0.f);
        acc.w += fmaxf(fmaf(vw, av.w, cv.w), 0.f);
    }
    __shared__ float4 sm[8];
    acc.x = warp_sum(acc.x); acc.y = warp_sum(acc.y);
    acc.z = warp_sum(acc.z); acc.w = warp_sum(acc.w);
    if ((tid & 31) == 0) sm[tid >> 5] = acc;
    __syncthreads();
    if (tid == 0) {
        float4 t = make_float4(0.f, 0.f, 0.f, 0.f);
#pragma unroll
        for (int i = 0; i < 8; i++) {
            t.x += sm[i].x; t.y += sm[i].y; t.z += sm[i].z; t.w += sm[i].w;
        }
        *(float4*)&g_feat[n * 4] =
            make_float4(t.x / 3136.f, t.y / 3136.f, t.z / 3136.f, t.w / 3136.f);
    }
}

// ---------------------------------------------------------------------------
// Quantum circuit (unchanged, passing since R0).
template <int Q>
__device__ __forceinline__ void ry_gate(float2* st, float t) {
    float s, c;
    sincosf(0.5f * t, &s, &c);
    const int m = 8 >> Q;
#pragma unroll
    for (int i = 0; i < 16; i++)
        if (!(i & m)) {
            float2 a0 = st[i], a1 = st[i | m];
            st[i]     = make_float2(c * a0.x - s * a1.x, c * a0.y - s * a1.y);
            st[i | m] = make_float2(s * a0.x + c * a1.x, s * a0.y + c * a1.y);
        }
}
template <int Q>
__device__ __forceinline__ void rz_gate(float2* st, float t) {
    float s, c;
    sincosf(0.5f * t, &s, &c);
    const int m = 8 >> Q;
#pragma unroll
    for (int i = 0; i < 16; i++)
        if (!(i & m)) {
            float2 a0 = st[i], a1 = st[i | m];
            st[i]     = make_float2(c * a0.x + s * a0.y, c * a0.y - s * a0.x);
            st[i | m] = make_float2(c * a1.x - s * a1.y, c * a1.y + s * a1.x);
        }
}
template <int Q>
__device__ __forceinline__ void rx_gate(float2* st, float t) {
    float s, c;
    sincosf(0.5f * t, &s, &c);
    const int m = 8 >> Q;
#pragma unroll
    for (int i = 0; i < 16; i++)
        if (!(i & m)) {
            float2 a0 = st[i], a1 = st[i | m];
            st[i]     = make_float2(c * a0.x + s * a1.y, c * a0.y - s * a1.x);
            st[i | m] = make_float2(c * a1.x + s * a0.y, c * a1.y - s * a0.x);
        }
}
template <int C, int T>
__device__ __forceinline__ void cnot_gate(float2* st) {
    const int mc = 8 >> C, mt = 8 >> T;
#pragma unroll
    for (int i = 0; i < 16; i++)
        if ((i & mc) && !(i & mt)) {
            float2 tmp = st[i];
            st[i] = st[i | mt];
            st[i | mt] = tmp;
        }
}

__global__ void k_final(const float* __restrict__ theta, const float* __restrict__ rho,
                        const float* __restrict__ ng, const float* __restrict__ nb,
                        float* __restrict__ out) {
    const int tid = threadIdx.x;  // 128 threads, one per batch element
    float f[4];
#pragma unroll
    for (int j = 0; j < 4; j++) f[j] = g_feat[tid * 4 + j];

    __shared__ double ssum, ssq;
    if (tid == 0) { ssum = 0.0; ssq = 0.0; }
    __syncthreads();
    float lf = f[0] + f[1] + f[2] + f[3];
    float lq = f[0] * f[0] + f[1] * f[1] + f[2] * f[2] + f[3] * f[3];
    float ws = warp_sum(lf), wq = warp_sum(lq);
    if ((tid & 31) == 0) { atomicAdd(&ssum, (double)ws); atomicAdd(&ssq, (double)wq); }
    __syncthreads();
    double mean = ssum / 512.0;
    double var1 = (ssq - 512.0 * mean * mean) / 511.0;
    if (var1 < 0.0) var1 = 0.0;
    float scale = (float)(3.14159265358979323846 / (sqrt(var1) + 1e-6));
    float sc[4];
#pragma unroll
    for (int j = 0; j < 4; j++) sc[j] = (float)((double)f[j] - mean) * scale;

    float2 st[16];
#pragma unroll
    for (int i = 0; i < 16; i++) st[i] = make_float2(0.f, 0.f);
    st[0].x = 1.f;

    ry_gate<0>(st, sc[0]); ry_gate<1>(st, sc[1]); ry_gate<2>(st, sc[2]); ry_gate<3>(st, sc[3]);

    ry_gate<0>(st, theta[0]);  rz_gate<0>(st, theta[1]);  rx_gate<0>(st, theta[2]);
    ry_gate<1>(st, theta[3]);  rz_gate<1>(st, theta[4]);  rx_gate<1>(st, theta[5]);
    ry_gate<2>(st, theta[6]);  rz_gate<2>(st, theta[7]);  rx_gate<2>(st, theta[8]);
    ry_gate<3>(st, theta[9]);  rz_gate<3>(st, theta[10]); rx_gate<3>(st, theta[11]);

    cnot_gate<0, 1>(st); cnot_gate<1, 2>(st); cnot_gate<2, 3>(st);

    ry_gate<0>(st, rho[0]);  rz_gate<0>(st, rho[1]);  rx_gate<0>(st, rho[2]);
    ry_gate<1>(st, rho[3]);  rz_gate<1>(st, rho[4]);  rx_gate<1>(st, rho[5]);
    ry_gate<2>(st, rho[6]);  rz_gate<2>(st, rho[7]);  rx_gate<2>(st, rho[8]);
    ry_gate<3>(st, rho[9]);  rz_gate<3>(st, rho[10]); rx_gate<3>(st, rho[11]);

    cnot_gate<1, 0>(st); cnot_gate<2, 1>(st); cnot_gate<3, 2>(st);

    float pr[16];
#pragma unroll
    for (int i = 0; i < 16; i++) pr[i] = st[i].x * st[i].x + st[i].y * st[i].y;

    float e[4];
#pragma unroll
    for (int q = 0; q < 4; q++) {
        const int m = 8 >> q;
        float acc = 0.f;
#pragma unroll
        for (int i = 0; i < 16; i++) acc += (i & m) ? -pr[i] : pr[i];
        e[q] = acc;
    }

    __shared__ double s1, s2;
#pragma unroll
    for (int j = 0; j < 4; j++) {
        if (tid == 0) { s1 = 0.0; s2 = 0.0; }
        __syncthreads();
        float v = e[j];
        float w1 = warp_sum(v), w2 = warp_sum(v * v);
        if ((tid & 31) == 0) { atomicAdd(&s1, (double)w1); atomicAdd(&s2, (double)w2); }
        __syncthreads();
        double mu = s1 / 128.0;
        double vv = s2 / 128.0 - mu * mu;
        out[tid * 4 + j] =
            (float)(((double)v - mu) * rsqrt(vv + 1e-5) * (double)ng[j] + (double)nb[j]);
        __syncthreads();
    }
}

// ---------------------------------------------------------------------------
extern "C" void kernel_launch(void* const* d_in, const int* in_sizes, int n_in,
                              void* d_out, int out_size) {
    const float* x     = (const float*)d_in[0];
    const float* w1    = (const float*)d_in[1];
    const float* b1    = (const float*)d_in[2];
    const float* bn1g  = (const float*)d_in[3];
    const float* bn1b  = (const float*)d_in[4];
    const float* w2    = (const float*)d_in[5];
    const float* b2    = (const float*)d_in[6];
    const float* bn2g  = (const float*)d_in[7];
    const float* bn2b  = (const float*)d_in[8];
    const float* theta = (const float*)d_in[9];
    const float* rho   = (const float*)d_in[10];
    const float* ng    = (const float*)d_in[11];
    const float* nbp   = (const float*)d_in[12];
    float* out = (float*)d_out;

    k_conv1<<<dim3(7, NB), 256>>>(x, w1, b1);
    k_fin1<<<1, 128>>>(bn1g, bn1b);
    k_conv2<<<dim3(14, NB), 224>>>(w2, b2);
    k_fin2<<<1, 128>>>(bn2g, bn2b);
    k_pool_mean<<<128, 256>>>();
    k_final<<<1, 128>>>(theta, rho, ng, nbp, out);
}

// round 5
// speedup vs baseline: 1.5691x; 1.1641x over previous
#include <cuda_runtime.h>
#include <math.h>

// ---------------------------------------------------------------------------
// QuantumNATExtendedQML — R4: fin kernels eliminated. Conv kernels atomically
// accumulate BN stats into tiny global arrays; consumer kernels recompute the
// BN affine per block in their prologue. k_final re-zeroes stats for graph
// replay. Pipeline: conv1 -> conv2 -> pool_mean -> final (4 launches).
// ---------------------------------------------------------------------------

#define NB 128

// persistent device scratch (no cudaMalloc allowed); zero-initialized.
__device__ double g_stats1[16];                            // sum[8], sumsq[8] conv1
__device__ double g_stats2[8];                             // sum[4], sumsq[4] conv2
__device__ __align__(16) float g_h1max[NB * 112 * 112 * 8];// pooled raw conv1 max, ch-last
__device__ __align__(16) float g_h1min[NB * 112 * 112 * 8];// pooled raw conv1 min, ch-last
__device__ __align__(16) float g_pmax[NB * 56 * 56 * 4];   // pooled raw conv2 max, ch-last
__device__ __align__(16) float g_pmin[NB * 56 * 56 * 4];   // pooled raw conv2 min, ch-last
__device__ __align__(16) float g_feat[NB * 4];

__device__ __forceinline__ float warp_sum(float v) {
#pragma unroll
    for (int o = 16; o > 0; o >>= 1) v += __shfl_xor_sync(0xffffffffu, v, o);
    return v;
}

// ---------------------------------------------------------------------------
// Fused conv1: raw conv output y -> global atomic (sum, sumsq) + 2x2 pooled
// raw max/min (ch-last) in one pass over x.
// grid(7, 128), block 256.  grp = tid/128 handles oc group grp*4..grp*4+3.
// pc = tid%128 (< 112 active) owns pooled column pc, strip of 32 conv rows.
__global__ void __launch_bounds__(256) k_conv1(const float* __restrict__ x,
                                               const float* __restrict__ w,
                                               const float* __restrict__ bias) {
    __shared__ float tile[34][226];
    __shared__ double sacc[16];
    const int n = blockIdx.y, h0 = blockIdx.x * 32, tid = threadIdx.x;
    const int grp = tid >> 7, pc = tid & 127;

    const float* xim = x + (size_t)n * 224 * 224;
    for (int i = tid; i < 34 * 226; i += 256) {
        int r = i / 226, c = i % 226;
        int hh = h0 - 1 + r, ww = c - 1;
        float v = 0.f;
        if (hh >= 0 && hh < 224 && ww >= 0 && ww < 224) v = xim[hh * 224 + ww];
        tile[r][c] = v;
    }
    if (tid < 16) sacc[tid] = 0.0;

    float wr[36], br[4];
#pragma unroll
    for (int j = 0; j < 4; j++) {
        int oc = grp * 4 + j;
#pragma unroll
        for (int k = 0; k < 9; k++) wr[j * 9 + k] = w[oc * 9 + k];
        br[j] = bias[oc];
    }
    __syncthreads();

    float s[4] = {0.f, 0.f, 0.f, 0.f}, q[4] = {0.f, 0.f, 0.f, 0.f};

    if (pc < 112) {
        const int c0 = 2 * pc;
        float t0[4], t1[4];
#pragma unroll
        for (int i = 0; i < 4; i++) { t0[i] = tile[0][c0 + i]; t1[i] = tile[1][c0 + i]; }
        float mx[4], mn[4];

        float* pmax = &g_h1max[(((size_t)n * 112 + blockIdx.x * 16) * 112 + pc) * 8 + grp * 4];
        float* pmin = &g_h1min[(((size_t)n * 112 + blockIdx.x * 16) * 112 + pc) * 8 + grp * 4];

#pragma unroll 2
        for (int r = 0; r < 32; r++) {
            float t2[4];
#pragma unroll
            for (int i = 0; i < 4; i++) t2[i] = tile[r + 2][c0 + i];
#pragma unroll
            for (int j = 0; j < 4; j++) {
                const float* wk = &wr[j * 9];
                float z0 = br[j], z1 = br[j];
                z0 = fmaf(wk[0], t0[0], z0); z1 = fmaf(wk[0], t0[1], z1);
                z0 = fmaf(wk[1], t0[1], z0); z1 = fmaf(wk[1], t0[2], z1);
                z0 = fmaf(wk[2], t0[2], z0); z1 = fmaf(wk[2], t0[3], z1);
                z0 = fmaf(wk[3], t1[0], z0); z1 = fmaf(wk[3], t1[1], z1);
                z0 = fmaf(wk[4], t1[1], z0); z1 = fmaf(wk[4], t1[2], z1);
                z0 = fmaf(wk[5], t1[2], z0); z1 = fmaf(wk[5], t1[3], z1);
                z0 = fmaf(wk[6], t2[0], z0); z1 = fmaf(wk[6], t2[1], z1);
                z0 = fmaf(wk[7], t2[1], z0); z1 = fmaf(wk[7], t2[2], z1);
                z0 = fmaf(wk[8], t2[2], z0); z1 = fmaf(wk[8], t2[3], z1);
                s[j] += z0 + z1;
                q[j] = fmaf(z0, z0, fmaf(z1, z1, q[j]));
                float hi = fmaxf(z0, z1), lo = fminf(z0, z1);
                if (r & 1) {
                    mx[j] = fmaxf(mx[j], hi);
                    mn[j] = fminf(mn[j], lo);
                } else {
                    mx[j] = hi;
                    mn[j] = lo;
                }
            }
            if (r & 1) {
                *(float4*)pmax = make_float4(mx[0], mx[1], mx[2], mx[3]);
                *(float4*)pmin = make_float4(mn[0], mn[1], mn[2], mn[3]);
                pmax += 112 * 8;
                pmin += 112 * 8;
            }
#pragma unroll
            for (int i = 0; i < 4; i++) { t0[i] = t1[i]; t1[i] = t2[i]; }
        }
    }

#pragma unroll
    for (int j = 0; j < 4; j++) {
        float ws = warp_sum(s[j]);
        float wq = warp_sum(q[j]);
        if ((tid & 31) == 0) {
            atomicAdd(&sacc[grp * 4 + j], (double)ws);
            atomicAdd(&sacc[8 + grp * 4 + j], (double)wq);
        }
    }
    __syncthreads();
    if (tid < 16) atomicAdd(&g_stats1[tid], sacc[tid]);
}

// ---------------------------------------------------------------------------
// conv2 (oc 0..3): per-block prologue derives bn1 affine from g_stats1;
// h reconstructed on tile load as relu(a1*sel(max,min)+c1); raw y2 stats go
// atomically to g_stats2; in-block 2x2 pooled raw max/min written out.
// grid(14, 128), block 224.
__global__ void __launch_bounds__(224) k_conv2(const float* __restrict__ w2,
                                               const float* __restrict__ b2,
                                               const float* __restrict__ bn1g,
                                               const float* __restrict__ bn1b) {
    __shared__ float tile[8][10][120];
    __shared__ float4 wq[72];
    __shared__ float4 ybuf[8][112];
    __shared__ float bsh[4], s_a1[8], s_c1[8];
    __shared__ double sacc[8];
    const int n = blockIdx.y, h0 = blockIdx.x * 8, tid = threadIdx.x;

    if (tid < 8) {
        double N = 128.0 * 224.0 * 224.0;
        double mu = g_stats1[tid] / N;
        double var = g_stats1[8 + tid] / N - mu * mu;
        double a = (double)bn1g[tid] * rsqrt(var + 1e-5);
        s_a1[tid] = (float)a;
        s_c1[tid] = (float)((double)bn1b[tid] - mu * a);
    }
    if (tid < 72)  // w2 layout [16][8][3][3]; pack oc 0..3 per (ic,k)
        wq[tid] = make_float4(w2[tid], w2[72 + tid], w2[144 + tid], w2[216 + tid]);
    if (tid < 4) bsh[tid] = b2[tid];
    if (tid < 8) sacc[tid] = 0.0;
    __syncthreads();

    float a1r[8], c1r[8];
#pragma unroll
    for (int ch = 0; ch < 8; ch++) { a1r[ch] = s_a1[ch]; c1r[ch] = s_c1[ch]; }

    for (int i = tid; i < 10 * 114; i += 224) {
        int r = i / 114, c = i % 114;
        int hh = h0 - 1 + r, ww = c - 1;
        float v[8];
        if (hh >= 0 && hh < 112 && ww >= 0 && ww < 112) {
            size_t base = (((size_t)n * 112 + hh) * 112 + ww) * 8;
            const float4* mx = (const float4*)&g_h1max[base];
            const float4* mn = (const float4*)&g_h1min[base];
            float4 x0 = mx[0], x1 = mx[1], n0 = mn[0], n1 = mn[1];
            float raw[8] = {a1r[0] >= 0.f ? x0.x : n0.x, a1r[1] >= 0.f ? x0.y : n0.y,
                            a1r[2] >= 0.f ? x0.z : n0.z, a1r[3] >= 0.f ? x0.w : n0.w,
                            a1r[4] >= 0.f ? x1.x : n1.x, a1r[5] >= 0.f ? x1.y : n1.y,
                            a1r[6] >= 0.f ? x1.z : n1.z, a1r[7] >= 0.f ? x1.w : n1.w};
#pragma unroll
            for (int ch = 0; ch < 8; ch++)
                v[ch] = fmaxf(fmaf(raw[ch], a1r[ch], c1r[ch]), 0.f);
        } else {
#pragma unroll
            for (int ch = 0; ch < 8; ch++) v[ch] = 0.f;
        }
#pragma unroll
        for (int ch = 0; ch < 8; ch++) tile[ch][r][c] = v[ch];
    }
    __syncthreads();

    const int r = tid / 28, g = tid % 28;
    float y[4][4];  // [oc][px]
    {
        float b0 = bsh[0], b1 = bsh[1], b2v = bsh[2], b3 = bsh[3];
#pragma unroll
        for (int p = 0; p < 4; p++) {
            y[0][p] = b0; y[1][p] = b1; y[2][p] = b2v; y[3][p] = b3;
        }
    }

#pragma unroll 1
    for (int ic = 0; ic < 8; ic++) {
#pragma unroll
        for (int kh = 0; kh < 3; kh++) {
            const float4 va = *(const float4*)&tile[ic][r + kh][4 * g];
            const float2 vb = *(const float2*)&tile[ic][r + kh][4 * g + 4];
            float t[6] = {va.x, va.y, va.z, va.w, vb.x, vb.y};
#pragma unroll
            for (int kw = 0; kw < 3; kw++) {
                float4 wv = wq[ic * 9 + kh * 3 + kw];
#pragma unroll
                for (int p = 0; p < 4; p++) {
                    float u = t[p + kw];
                    y[0][p] = fmaf(wv.x, u, y[0][p]);
                    y[1][p] = fmaf(wv.y, u, y[1][p]);
                    y[2][p] = fmaf(wv.z, u, y[2][p]);
                    y[3][p] = fmaf(wv.w, u, y[3][p]);
                }
            }
        }
    }

    // bn2 stats on raw y2
#pragma unroll
    for (int j = 0; j < 4; j++) {
        float s = (y[j][0] + y[j][1]) + (y[j][2] + y[j][3]);
        float qq = fmaf(y[j][0], y[j][0], fmaf(y[j][1], y[j][1],
                   fmaf(y[j][2], y[j][2], y[j][3] * y[j][3])));
        float ws = warp_sum(s);
        float wq = warp_sum(qq);
        if ((tid & 31) == 0) {
            atomicAdd(&sacc[j], (double)ws);
            atomicAdd(&sacc[4 + j], (double)wq);
        }
    }

    // stash y into ybuf for in-block 2x2 pooling
#pragma unroll
    for (int p = 0; p < 4; p++)
        ybuf[r][4 * g + p] = make_float4(y[0][p], y[1][p], y[2][p], y[3][p]);
    __syncthreads();

    // 224 threads = 4 pooled rows x 56 pooled cols
    {
        const int ppr = tid / 56, ppw = tid % 56;
        float4 u0 = ybuf[2 * ppr][2 * ppw];
        float4 u1 = ybuf[2 * ppr][2 * ppw + 1];
        float4 u2 = ybuf[2 * ppr + 1][2 * ppw];
        float4 u3 = ybuf[2 * ppr + 1][2 * ppw + 1];
        float4 mx, mn;
        mx.x = fmaxf(fmaxf(u0.x, u1.x), fmaxf(u2.x, u3.x));
        mx.y = fmaxf(fmaxf(u0.y, u1.y), fmaxf(u2.y, u3.y));
        mx.z = fmaxf(fmaxf(u0.z, u1.z), fmaxf(u2.z, u3.z));
        mx.w = fmaxf(fmaxf(u0.w, u1.w), fmaxf(u2.w, u3.w));
        mn.x = fminf(fminf(u0.x, u1.x), fminf(u2.x, u3.x));
        mn.y = fminf(fminf(u0.y, u1.y), fminf(u2.y, u3.y));
        mn.z = fminf(fminf(u0.z, u1.z), fminf(u2.z, u3.z));
        mn.w = fminf(fminf(u0.w, u1.w), fminf(u2.w, u3.w));
        size_t o = (((size_t)n * 56 + (blockIdx.x * 4 + ppr)) * 56 + ppw) * 4;
        *(float4*)&g_pmax[o] = mx;
        *(float4*)&g_pmin[o] = mn;
    }
    if (tid < 8) atomicAdd(&g_stats2[tid], sacc[tid]);
}

// ---------------------------------------------------------------------------
// feat = mean over 56x56 of relu(a2*sel(pmax,pmin)+c2); bn2 affine derived
// per block from g_stats2.  grid(128), block 256.
__global__ void k_pool_mean(const float* __restrict__ bn2g,
                            const float* __restrict__ bn2b) {
    __shared__ float s_a2[4], s_c2[4];
    const int n = blockIdx.x, tid = threadIdx.x;
    if (tid < 4) {
        double N = 128.0 * 112.0 * 112.0;
        double mu = g_stats2[tid] / N;
        double var = g_stats2[4 + tid] / N - mu * mu;
        double a = (double)bn2g[tid] * rsqrt(var + 1e-5);
        s_a2[tid] = (float)a;
        s_c2[tid] = (float)((double)bn2b[tid] - mu * a);
    }
    __syncthreads();
    const float4 av = *(const float4*)s_a2;
    const float4 cv = *(const float4*)s_c2;
    const float4* pmax = (const float4*)&g_pmax[(size_t)n * 56 * 56 * 4];
    const float4* pmin = (const float4*)&g_pmin[(size_t)n * 56 * 56 * 4];
    float4 acc = make_float4(0.f, 0.f, 0.f, 0.f);

    for (int p = tid; p < 56 * 56; p += 256) {
        float4 mx = pmax[p], mn = pmin[p];
        float vx = av.x >= 0.f ? mx.x : mn.x;
        float vy = av.y >= 0.f ? mx.y : mn.y;
        float vz = av.z >= 0.f ? mx.z : mn.z;
        float vw = av.w >= 0.f ? mx.w : mn.w;
        acc.x += fmaxf(fmaf(vx, av.x, cv.x), 0.f);
        acc.y += fmaxf(fmaf(vy, av.y, cv.y), 0.f);
        acc.z += fmaxf(fmaf(vz, av.z, cv.z), 0.f);
        acc.w += fmaxf(fmaf(vw, av.w, cv.w), 0.f);
    }
    __shared__ float4 sm[8];
    acc.x = warp_sum(acc.x); acc.y = warp_sum(acc.y);
    acc.z = warp_sum(acc.z); acc.w = warp_sum(acc.w);
    if ((tid & 31) == 0) sm[tid >> 5] = acc;
    __syncthreads();
    if (tid == 0) {
        float4 t = make_float4(0.f, 0.f, 0.f, 0.f);
#pragma unroll
        for (int i = 0; i < 8; i++) {
            t.x += sm[i].x; t.y += sm[i].y; t.z += sm[i].z; t.w += sm[i].w;
        }
        *(float4*)&g_feat[n * 4] =
            make_float4(t.x / 3136.f, t.y / 3136.f, t.z / 3136.f, t.w / 3136.f);
    }
}

// ---------------------------------------------------------------------------
// Quantum circuit (unchanged, passing since R0).
template <int Q>
__device__ __forceinline__ void ry_gate(float2* st, float t) {
    float s, c;
    sincosf(0.5f * t, &s, &c);
    const int m = 8 >> Q;
#pragma unroll
    for (int i = 0; i < 16; i++)
        if (!(i & m)) {
            float2 a0 = st[i], a1 = st[i | m];
            st[i]     = make_float2(c * a0.x - s * a1.x, c * a0.y - s * a1.y);
            st[i | m] = make_float2(s * a0.x + c * a1.x, s * a0.y + c * a1.y);
        }
}
template <int Q>
__device__ __forceinline__ void rz_gate(float2* st, float t) {
    float s, c;
    sincosf(0.5f * t, &s, &c);
    const int m = 8 >> Q;
#pragma unroll
    for (int i = 0; i < 16; i++)
        if (!(i & m)) {
            float2 a0 = st[i], a1 = st[i | m];
            st[i]     = make_float2(c * a0.x + s * a0.y, c * a0.y - s * a0.x);
            st[i | m] = make_float2(c * a1.x - s * a1.y, c * a1.y + s * a1.x);
        }
}
template <int Q>
__device__ __forceinline__ void rx_gate(float2* st, float t) {
    float s, c;
    sincosf(0.5f * t, &s, &c);
    const int m = 8 >> Q;
#pragma unroll
    for (int i = 0; i < 16; i++)
        if (!(i & m)) {
            float2 a0 = st[i], a1 = st[i | m];
            st[i]     = make_float2(c * a0.x + s * a1.y, c * a0.y - s * a1.x);
            st[i | m] = make_float2(c * a1.x + s * a0.y, c * a1.y - s * a0.x);
        }
}
template <int C, int T>
__device__ __forceinline__ void cnot_gate(float2* st) {
    const int mc = 8 >> C, mt = 8 >> T;
#pragma unroll
    for (int i = 0; i < 16; i++)
        if ((i & mc) && !(i & mt)) {
            float2 tmp = st[i];
            st[i] = st[i | mt];
            st[i | mt] = tmp;
        }
}

__global__ void k_final(const float* __restrict__ theta, const float* __restrict__ rho,
                        const float* __restrict__ ng, const float* __restrict__ nb,
                        float* __restrict__ out) {
    const int tid = threadIdx.x;  // 128 threads, one per batch element

    // restore stats to zero for the next (graph-replayed) launch
    if (tid < 16) g_stats1[tid] = 0.0;
    if (tid < 8) g_stats2[tid] = 0.0;

    float f[4];
#pragma unroll
    for (int j = 0; j < 4; j++) f[j] = g_feat[tid * 4 + j];

    __shared__ double ssum, ssq;
    if (tid == 0) { ssum = 0.0; ssq = 0.0; }
    __syncthreads();
    float lf = f[0] + f[1] + f[2] + f[3];
    float lq = f[0] * f[0] + f[1] * f[1] + f[2] * f[2] + f[3] * f[3];
    float ws = warp_sum(lf), wq = warp_sum(lq);
    if ((tid & 31) == 0) { atomicAdd(&ssum, (double)ws); atomicAdd(&ssq, (double)wq); }
    __syncthreads();
    double mean = ssum / 512.0;
    double var1 = (ssq - 512.0 * mean * mean) / 511.0;
    if (var1 < 0.0) var1 = 0.0;
    float scale = (float)(3.14159265358979323846 / (sqrt(var1) + 1e-6));
    float sc[4];
#pragma unroll
    for (int j = 0; j < 4; j++) sc[j] = (float)((double)f[j] - mean) * scale;

    float2 st[16];
#pragma unroll
    for (int i = 0; i < 16; i++) st[i] = make_float2(0.f, 0.f);
    st[0].x = 1.f;

    ry_gate<0>(st, sc[0]); ry_gate<1>(st, sc[1]); ry_gate<2>(st, sc[2]); ry_gate<3>(st, sc[3]);

    ry_gate<0>(st, theta[0]);  rz_gate<0>(st, theta[1]);  rx_gate<0>(st, theta[2]);
    ry_gate<1>(st, theta[3]);  rz_gate<1>(st, theta[4]);  rx_gate<1>(st, theta[5]);
    ry_gate<2>(st, theta[6]);  rz_gate<2>(st, theta[7]);  rx_gate<2>(st, theta[8]);
    ry_gate<3>(st, theta[9]);  rz_gate<3>(st, theta[10]); rx_gate<3>(st, theta[11]);

    cnot_gate<0, 1>(st); cnot_gate<1, 2>(st); cnot_gate<2, 3>(st);

    ry_gate<0>(st, rho[0]);  rz_gate<0>(st, rho[1]);  rx_gate<0>(st, rho[2]);
    ry_gate<1>(st, rho[3]);  rz_gate<1>(st, rho[4]);  rx_gate<1>(st, rho[5]);
    ry_gate<2>(st, rho[6]);  rz_gate<2>(st, rho[7]);  rx_gate<2>(st, rho[8]);
    ry_gate<3>(st, rho[9]);  rz_gate<3>(st, rho[10]); rx_gate<3>(st, rho[11]);

    cnot_gate<1, 0>(st); cnot_gate<2, 1>(st); cnot_gate<3, 2>(st);

    float pr[16];
#pragma unroll
    for (int i = 0; i < 16; i++) pr[i] = st[i].x * st[i].x + st[i].y * st[i].y;

    float e[4];
#pragma unroll
    for (int q = 0; q < 4; q++) {
        const int m = 8 >> q;
        float acc = 0.f;
#pragma unroll
        for (int i = 0; i < 16; i++) acc += (i & m) ? -pr[i] : pr[i];
        e[q] = acc;
    }

    __shared__ double s1, s2;
#pragma unroll
    for (int j = 0; j < 4; j++) {
        if (tid == 0) { s1 = 0.0; s2 = 0.0; }
        __syncthreads();
        float v = e[j];
        float w1 = warp_sum(v), w2 = warp_sum(v * v);
        if ((tid & 31) == 0) { atomicAdd(&s1, (double)w1); atomicAdd(&s2, (double)w2); }
        __syncthreads();
        double mu = s1 / 128.0;
        double vv = s2 / 128.0 - mu * mu;
        out[tid * 4 + j] =
            (float)(((double)v - mu) * rsqrt(vv + 1e-5) * (double)ng[j] + (double)nb[j]);
        __syncthreads();
    }
}

// ---------------------------------------------------------------------------
extern "C" void kernel_launch(void* const* d_in, const int* in_sizes, int n_in,
                              void* d_out, int out_size) {
    const float* x     = (const float*)d_in[0];
    const float* w1    = (const float*)d_in[1];
    const float* b1    = (const float*)d_in[2];
    const float* bn1g  = (const float*)d_in[3];
    const float* bn1b  = (const float*)d_in[4];
    const float* w2    = (const float*)d_in[5];
    const float* b2    = (const float*)d_in[6];
    const float* bn2g  = (const float*)d_in[7];
    const float* bn2b  = (const float*)d_in[8];
    const float* theta = (const float*)d_in[9];
    const float* rho   = (const float*)d_in[10];
    const float* ng    = (const float*)d_in[11];
    const float* nbp   = (const float*)d_in[12];
    float* out = (float*)d_out;

    k_conv1<<<dim3(7, NB), 256>>>(x, w1, b1);
    k_conv2<<<dim3(14, NB), 224>>>(w2, b2, bn1g, bn1b);
    k_pool_mean<<<128, 256>>>(bn2g, bn2b);
    k_final<<<1, 128>>>(theta, rho, ng, nbp, out);
}

// round 6
// speedup vs baseline: 1.5770x; 1.0051x over previous
#include <cuda_runtime.h>
#include <math.h>

// ---------------------------------------------------------------------------
// QuantumNATExtendedQML — R5: k_final fused into k_pool_mean via
// last-block-done pattern. Pipeline: conv1 -> conv2 -> pool_mean+final
// (3 launches). Conv kernels unchanged from R4 (near FFMA issue floor).
// ---------------------------------------------------------------------------

#define NB 128

// persistent device scratch (no cudaMalloc allowed); zero-initialized.
__device__ double g_stats1[16];                            // sum[8], sumsq[8] conv1
__device__ double g_stats2[8];                             // sum[4], sumsq[4] conv2
__device__ unsigned int g_done;                            // pool-block counter
__device__ __align__(16) float g_h1max[NB * 112 * 112 * 8];// pooled raw conv1 max, ch-last
__device__ __align__(16) float g_h1min[NB * 112 * 112 * 8];// pooled raw conv1 min, ch-last
__device__ __align__(16) float g_pmax[NB * 56 * 56 * 4];   // pooled raw conv2 max, ch-last
__device__ __align__(16) float g_pmin[NB * 56 * 56 * 4];   // pooled raw conv2 min, ch-last
__device__ __align__(16) float g_feat[NB * 4];

__device__ __forceinline__ float warp_sum(float v) {
#pragma unroll
    for (int o = 16; o > 0; o >>= 1) v += __shfl_xor_sync(0xffffffffu, v, o);
    return v;
}

// ---------------------------------------------------------------------------
// Fused conv1: raw conv output y -> global atomic (sum, sumsq) + 2x2 pooled
// raw max/min (ch-last) in one pass over x.
// grid(7, 128), block 256.  grp = tid/128 handles oc group grp*4..grp*4+3.
// pc = tid%128 (< 112 active) owns pooled column pc, strip of 32 conv rows.
__global__ void __launch_bounds__(256) k_conv1(const float* __restrict__ x,
                                               const float* __restrict__ w,
                                               const float* __restrict__ bias) {
    __shared__ float tile[34][226];
    __shared__ double sacc[16];
    const int n = blockIdx.y, h0 = blockIdx.x * 32, tid = threadIdx.x;
    const int grp = tid >> 7, pc = tid & 127;

    const float* xim = x + (size_t)n * 224 * 224;
    for (int i = tid; i < 34 * 226; i += 256) {
        int r = i / 226, c = i % 226;
        int hh = h0 - 1 + r, ww = c - 1;
        float v = 0.f;
        if (hh >= 0 && hh < 224 && ww >= 0 && ww < 224) v = xim[hh * 224 + ww];
        tile[r][c] = v;
    }
    if (tid < 16) sacc[tid] = 0.0;

    float wr[36], br[4];
#pragma unroll
    for (int j = 0; j < 4; j++) {
        int oc = grp * 4 + j;
#pragma unroll
        for (int k = 0; k < 9; k++) wr[j * 9 + k] = w[oc * 9 + k];
        br[j] = bias[oc];
    }
    __syncthreads();

    float s[4] = {0.f, 0.f, 0.f, 0.f}, q[4] = {0.f, 0.f, 0.f, 0.f};

    if (pc < 112) {
        const int c0 = 2 * pc;
        float t0[4], t1[4];
#pragma unroll
        for (int i = 0; i < 4; i++) { t0[i] = tile[0][c0 + i]; t1[i] = tile[1][c0 + i]; }
        float mx[4], mn[4];

        float* pmax = &g_h1max[(((size_t)n * 112 + blockIdx.x * 16) * 112 + pc) * 8 + grp * 4];
        float* pmin = &g_h1min[(((size_t)n * 112 + blockIdx.x * 16) * 112 + pc) * 8 + grp * 4];

#pragma unroll 2
        for (int r = 0; r < 32; r++) {
            float t2[4];
#pragma unroll
            for (int i = 0; i < 4; i++) t2[i] = tile[r + 2][c0 + i];
#pragma unroll
            for (int j = 0; j < 4; j++) {
                const float* wk = &wr[j * 9];
                float z0 = br[j], z1 = br[j];
                z0 = fmaf(wk[0], t0[0], z0); z1 = fmaf(wk[0], t0[1], z1);
                z0 = fmaf(wk[1], t0[1], z0); z1 = fmaf(wk[1], t0[2], z1);
                z0 = fmaf(wk[2], t0[2], z0); z1 = fmaf(wk[2], t0[3], z1);
                z0 = fmaf(wk[3], t1[0], z0); z1 = fmaf(wk[3], t1[1], z1);
                z0 = fmaf(wk[4], t1[1], z0); z1 = fmaf(wk[4], t1[2], z1);
                z0 = fmaf(wk[5], t1[2], z0); z1 = fmaf(wk[5], t1[3], z1);
                z0 = fmaf(wk[6], t2[0], z0); z1 = fmaf(wk[6], t2[1], z1);
                z0 = fmaf(wk[7], t2[1], z0); z1 = fmaf(wk[7], t2[2], z1);
                z0 = fmaf(wk[8], t2[2], z0); z1 = fmaf(wk[8], t2[3], z1);
                s[j] += z0 + z1;
                q[j] = fmaf(z0, z0, fmaf(z1, z1, q[j]));
                float hi = fmaxf(z0, z1), lo = fminf(z0, z1);
                if (r & 1) {
                    mx[j] = fmaxf(mx[j], hi);
                    mn[j] = fminf(mn[j], lo);
                } else {
                    mx[j] = hi;
                    mn[j] = lo;
                }
            }
            if (r & 1) {
                *(float4*)pmax = make_float4(mx[0], mx[1], mx[2], mx[3]);
                *(float4*)pmin = make_float4(mn[0], mn[1], mn[2], mn[3]);
                pmax += 112 * 8;
                pmin += 112 * 8;
            }
#pragma unroll
            for (int i = 0; i < 4; i++) { t0[i] = t1[i]; t1[i] = t2[i]; }
        }
    }

#pragma unroll
    for (int j = 0; j < 4; j++) {
        float ws = warp_sum(s[j]);
        float wq = warp_sum(q[j]);
        if ((tid & 31) == 0) {
            atomicAdd(&sacc[grp * 4 + j], (double)ws);
            atomicAdd(&sacc[8 + grp * 4 + j], (double)wq);
        }
    }
    __syncthreads();
    if (tid < 16) atomicAdd(&g_stats1[tid], sacc[tid]);
}

// ---------------------------------------------------------------------------
// conv2 (oc 0..3): per-block prologue derives bn1 affine from g_stats1;
// h reconstructed on tile load as relu(a1*sel(max,min)+c1); raw y2 stats go
// atomically to g_stats2; in-block 2x2 pooled raw max/min written out.
// grid(14, 128), block 224.
__global__ void __launch_bounds__(224) k_conv2(const float* __restrict__ w2,
                                               const float* __restrict__ b2,
                                               const float* __restrict__ bn1g,
                                               const float* __restrict__ bn1b) {
    __shared__ float tile[8][10][120];
    __shared__ float4 wq[72];
    __shared__ float4 ybuf[8][112];
    __shared__ float bsh[4], s_a1[8], s_c1[8];
    __shared__ double sacc[8];
    const int n = blockIdx.y, h0 = blockIdx.x * 8, tid = threadIdx.x;

    if (tid < 8) {
        double N = 128.0 * 224.0 * 224.0;
        double mu = g_stats1[tid] / N;
        double var = g_stats1[8 + tid] / N - mu * mu;
        double a = (double)bn1g[tid] * rsqrt(var + 1e-5);
        s_a1[tid] = (float)a;
        s_c1[tid] = (float)((double)bn1b[tid] - mu * a);
    }
    if (tid < 72)  // w2 layout [16][8][3][3]; pack oc 0..3 per (ic,k)
        wq[tid] = make_float4(w2[tid], w2[72 + tid], w2[144 + tid], w2[216 + tid]);
    if (tid < 4) bsh[tid] = b2[tid];
    if (tid < 8) sacc[tid] = 0.0;
    __syncthreads();

    float a1r[8], c1r[8];
#pragma unroll
    for (int ch = 0; ch < 8; ch++) { a1r[ch] = s_a1[ch]; c1r[ch] = s_c1[ch]; }

    for (int i = tid; i < 10 * 114; i += 224) {
        int r = i / 114, c = i % 114;
        int hh = h0 - 1 + r, ww = c - 1;
        float v[8];
        if (hh >= 0 && hh < 112 && ww >= 0 && ww < 112) {
            size_t base = (((size_t)n * 112 + hh) * 112 + ww) * 8;
            const float4* mx = (const float4*)&g_h1max[base];
            const float4* mn = (const float4*)&g_h1min[base];
            float4 x0 = mx[0], x1 = mx[1], n0 = mn[0], n1 = mn[1];
            float raw[8] = {a1r[0] >= 0.f ? x0.x : n0.x, a1r[1] >= 0.f ? x0.y : n0.y,
                            a1r[2] >= 0.f ? x0.z : n0.z, a1r[3] >= 0.f ? x0.w : n0.w,
                            a1r[4] >= 0.f ? x1.x : n1.x, a1r[5] >= 0.f ? x1.y : n1.y,
                            a1r[6] >= 0.f ? x1.z : n1.z, a1r[7] >= 0.f ? x1.w : n1.w};
#pragma unroll
            for (int ch = 0; ch < 8; ch++)
                v[ch] = fmaxf(fmaf(raw[ch], a1r[ch], c1r[ch]), 0.f);
        } else {
#pragma unroll
            for (int ch = 0; ch < 8; ch++) v[ch] = 0.f;
        }
#pragma unroll
        for (int ch = 0; ch < 8; ch++) tile[ch][r][c] = v[ch];
    }
    __syncthreads();

    const int r = tid / 28, g = tid % 28;
    float y[4][4];  // [oc][px]
    {
        float b0 = bsh[0], b1 = bsh[1], b2v = bsh[2], b3 = bsh[3];
#pragma unroll
        for (int p = 0; p < 4; p++) {
            y[0][p] = b0; y[1][p] = b1; y[2][p] = b2v; y[3][p] = b3;
        }
    }

#pragma unroll 1
    for (int ic = 0; ic < 8; ic++) {
#pragma unroll
        for (int kh = 0; kh < 3; kh++) {
            const float4 va = *(const float4*)&tile[ic][r + kh][4 * g];
            const float2 vb = *(const float2*)&tile[ic][r + kh][4 * g + 4];
            float t[6] = {va.x, va.y, va.z, va.w, vb.x, vb.y};
#pragma unroll
            for (int kw = 0; kw < 3; kw++) {
                float4 wv = wq[ic * 9 + kh * 3 + kw];
#pragma unroll
                for (int p = 0; p < 4; p++) {
                    float u = t[p + kw];
                    y[0][p] = fmaf(wv.x, u, y[0][p]);
                    y[1][p] = fmaf(wv.y, u, y[1][p]);
                    y[2][p] = fmaf(wv.z, u, y[2][p]);
                    y[3][p] = fmaf(wv.w, u, y[3][p]);
                }
            }
        }
    }

    // bn2 stats on raw y2
#pragma unroll
    for (int j = 0; j < 4; j++) {
        float s = (y[j][0] + y[j][1]) + (y[j][2] + y[j][3]);
        float qq = fmaf(y[j][0], y[j][0], fmaf(y[j][1], y[j][1],
                   fmaf(y[j][2], y[j][2], y[j][3] * y[j][3])));
        float ws = warp_sum(s);
        float wq = warp_sum(qq);
        if ((tid & 31) == 0) {
            atomicAdd(&sacc[j], (double)ws);
            atomicAdd(&sacc[4 + j], (double)wq);
        }
    }

    // stash y into ybuf for in-block 2x2 pooling
#pragma unroll
    for (int p = 0; p < 4; p++)
        ybuf[r][4 * g + p] = make_float4(y[0][p], y[1][p], y[2][p], y[3][p]);
    __syncthreads();

    // 224 threads = 4 pooled rows x 56 pooled cols
    {
        const int ppr = tid / 56, ppw = tid % 56;
        float4 u0 = ybuf[2 * ppr][2 * ppw];
        float4 u1 = ybuf[2 * ppr][2 * ppw + 1];
        float4 u2 = ybuf[2 * ppr + 1][2 * ppw];
        float4 u3 = ybuf[2 * ppr + 1][2 * ppw + 1];
        float4 mx, mn;
        mx.x = fmaxf(fmaxf(u0.x, u1.x), fmaxf(u2.x, u3.x));
        mx.y = fmaxf(fmaxf(u0.y, u1.y), fmaxf(u2.y, u3.y));
        mx.z = fmaxf(fmaxf(u0.z, u1.z), fmaxf(u2.z, u3.z));
        mx.w = fmaxf(fmaxf(u0.w, u1.w), fmaxf(u2.w, u3.w));
        mn.x = fminf(fminf(u0.x, u1.x), fminf(u2.x, u3.x));
        mn.y = fminf(fminf(u0.y, u1.y), fminf(u2.y, u3.y));
        mn.z = fminf(fminf(u0.z, u1.z), fminf(u2.z, u3.z));
        mn.w = fminf(fminf(u0.w, u1.w), fminf(u2.w, u3.w));
        size_t o = (((size_t)n * 56 + (blockIdx.x * 4 + ppr)) * 56 + ppw) * 4;
        *(float4*)&g_pmax[o] = mx;
        *(float4*)&g_pmin[o] = mn;
    }
    if (tid < 8) atomicAdd(&g_stats2[tid], sacc[tid]);
}

// ---------------------------------------------------------------------------
// Quantum circuit helpers.
template <int Q>
__device__ __forceinline__ void ry_gate(float2* st, float t) {
    float s, c;
    sincosf(0.5f * t, &s, &c);
    const int m = 8 >> Q;
#pragma unroll
    for (int i = 0; i < 16; i++)
        if (!(i & m)) {
            float2 a0 = st[i], a1 = st[i | m];
            st[i]     = make_float2(c * a0.x - s * a1.x, c * a0.y - s * a1.y);
            st[i | m] = make_float2(s * a0.x + c * a1.x, s * a0.y + c * a1.y);
        }
}
template <int Q>
__device__ __forceinline__ void rz_gate(float2* st, float t) {
    float s, c;
    sincosf(0.5f * t, &s, &c);
    const int m = 8 >> Q;
#pragma unroll
    for (int i = 0; i < 16; i++)
        if (!(i & m)) {
            float2 a0 = st[i], a1 = st[i | m];
            st[i]     = make_float2(c * a0.x + s * a0.y, c * a0.y - s * a0.x);
            st[i | m] = make_float2(c * a1.x - s * a1.y, c * a1.y + s * a1.x);
        }
}
template <int Q>
__device__ __forceinline__ void rx_gate(float2* st, float t) {
    float s, c;
    sincosf(0.5f * t, &s, &c);
    const int m = 8 >> Q;
#pragma unroll
    for (int i = 0; i < 16; i++)
        if (!(i & m)) {
            float2 a0 = st[i], a1 = st[i | m];
            st[i]     = make_float2(c * a0.x + s * a1.y, c * a0.y - s * a1.x);
            st[i | m] = make_float2(c * a1.x + s * a0.y, c * a1.y - s * a0.x);
        }
}
template <int C, int T>
__device__ __forceinline__ void cnot_gate(float2* st) {
    const int mc = 8 >> C, mt = 8 >> T;
#pragma unroll
    for (int i = 0; i < 16; i++)
        if ((i & mc) && !(i & mt)) {
            float2 tmp = st[i];
            st[i] = st[i | mt];
            st[i | mt] = tmp;
        }
}

// ---------------------------------------------------------------------------
// pool_mean + fused final: each block computes feat[n]; the last block to
// finish (counter) runs standardize + circuit + output BN and resets state.
// grid(128), block 256.
__global__ void k_pool_final(const float* __restrict__ bn2g,
                             const float* __restrict__ bn2b,
                             const float* __restrict__ theta,
                             const float* __restrict__ rho,
                             const float* __restrict__ ng,
                             const float* __restrict__ nb,
                             float* __restrict__ out) {
    __shared__ float s_a2[4], s_c2[4];
    __shared__ unsigned int s_last;
    const int n = blockIdx.x, tid = threadIdx.x;
    if (tid < 4) {
        double N = 128.0 * 112.0 * 112.0;
        double mu = g_stats2[tid] / N;
        double var = g_stats2[4 + tid] / N - mu * mu;
        double a = (double)bn2g[tid] * rsqrt(var + 1e-5);
        s_a2[tid] = (float)a;
        s_c2[tid] = (float)((double)bn2b[tid] - mu * a);
    }
    __syncthreads();
    const float4 av = *(const float4*)s_a2;
    const float4 cv = *(const float4*)s_c2;
    const float4* pmax = (const float4*)&g_pmax[(size_t)n * 56 * 56 * 4];
    const float4* pmin = (const float4*)&g_pmin[(size_t)n * 56 * 56 * 4];
    float4 acc = make_float4(0.f, 0.f, 0.f, 0.f);

    for (int p = tid; p < 56 * 56; p += 256) {
        float4 mx = pmax[p], mn = pmin[p];
        float vx = av.x >= 0.f ? mx.x : mn.x;
        float vy = av.y >= 0.f ? mx.y : mn.y;
        float vz = av.z >= 0.f ? mx.z : mn.z;
        float vw = av.w >= 0.f ? mx.w : mn.w;
        acc.x += fmaxf(fmaf(vx, av.x, cv.x), 0.f);
        acc.y += fmaxf(fmaf(vy, av.y, cv.y), 0.f);
        acc.z += fmaxf(fmaf(vz, av.z, cv.z), 0.f);
        acc.w += fmaxf(fmaf(vw, av.w, cv.w), 0.f);
    }
    __shared__ float4 sm[8];
    acc.x = warp_sum(acc.x); acc.y = warp_sum(acc.y);
    acc.z = warp_sum(acc.z); acc.w = warp_sum(acc.w);
    if ((tid & 31) == 0) sm[tid >> 5] = acc;
    __syncthreads();
    if (tid == 0) {
        float4 t = make_float4(0.f, 0.f, 0.f, 0.f);
#pragma unroll
        for (int i = 0; i < 8; i++) {
            t.x += sm[i].x; t.y += sm[i].y; t.z += sm[i].z; t.w += sm[i].w;
        }
        *(float4*)&g_feat[n * 4] =
            make_float4(t.x / 3136.f, t.y / 3136.f, t.z / 3136.f, t.w / 3136.f);
        __threadfence();
        s_last = atomicAdd(&g_done, 1u);
    }
    __syncthreads();
    if (s_last != NB - 1) return;   // not the last block: done
    __threadfence();                // acquire: all g_feat writes visible

    // ---- fused final phase: threads 0..127 (one per batch element) ----
    if (tid == 0) {
        g_done = 0;                 // reset for graph replay
    }
    if (tid < 16) g_stats1[tid] = 0.0;
    if (tid < 8)  g_stats2[tid] = 0.0;
    if (tid >= 128) return;         // sm_70+: barriers ignore exited threads

    float f[4];
#pragma unroll
    for (int j = 0; j < 4; j++) f[j] = g_feat[tid * 4 + j];

    __shared__ double ssum, ssq;
    if (tid == 0) { ssum = 0.0; ssq = 0.0; }
    __syncthreads();
    float lf = f[0] + f[1] + f[2] + f[3];
    float lq = f[0] * f[0] + f[1] * f[1] + f[2] * f[2] + f[3] * f[3];
    float ws = warp_sum(lf), wq = warp_sum(lq);
    if ((tid & 31) == 0) { atomicAdd(&ssum, (double)ws); atomicAdd(&ssq, (double)wq); }
    __syncthreads();
    double mean = ssum / 512.0;
    double var1 = (ssq - 512.0 * mean * mean) / 511.0;
    if (var1 < 0.0) var1 = 0.0;
    float scale = (float)(3.14159265358979323846 / (sqrt(var1) + 1e-6));
    float sc[4];
#pragma unroll
    for (int j = 0; j < 4; j++) sc[j] = (float)((double)f[j] - mean) * scale;

    float2 st[16];
#pragma unroll
    for (int i = 0; i < 16; i++) st[i] = make_float2(0.f, 0.f);
    st[0].x = 1.f;

    ry_gate<0>(st, sc[0]); ry_gate<1>(st, sc[1]); ry_gate<2>(st, sc[2]); ry_gate<3>(st, sc[3]);

    ry_gate<0>(st, theta[0]);  rz_gate<0>(st, theta[1]);  rx_gate<0>(st, theta[2]);
    ry_gate<1>(st, theta[3]);  rz_gate<1>(st, theta[4]);  rx_gate<1>(st, theta[5]);
    ry_gate<2>(st, theta[6]);  rz_gate<2>(st, theta[7]);  rx_gate<2>(st, theta[8]);
    ry_gate<3>(st, theta[9]);  rz_gate<3>(st, theta[10]); rx_gate<3>(st, theta[11]);

    cnot_gate<0, 1>(st); cnot_gate<1, 2>(st); cnot_gate<2, 3>(st);

    ry_gate<0>(st, rho[0]);  rz_gate<0>(st, rho[1]);  rx_gate<0>(st, rho[2]);
    ry_gate<1>(st, rho[3]);  rz_gate<1>(st, rho[4]);  rx_gate<1>(st, rho[5]);
    ry_gate<2>(st, rho[6]);  rz_gate<2>(st, rho[7]);  rx_gate<2>(st, rho[8]);
    ry_gate<3>(st, rho[9]);  rz_gate<3>(st, rho[10]); rx_gate<3>(st, rho[11]);

    cnot_gate<1, 0>(st); cnot_gate<2, 1>(st); cnot_gate<3, 2>(st);

    float pr[16];
#pragma unroll
    for (int i = 0; i < 16; i++) pr[i] = st[i].x * st[i].x + st[i].y * st[i].y;

    float e[4];
#pragma unroll
    for (int q = 0; q < 4; q++) {
        const int m = 8 >> q;
        float a = 0.f;
#pragma unroll
        for (int i = 0; i < 16; i++) a += (i & m) ? -pr[i] : pr[i];
        e[q] = a;
    }

    __shared__ double s1, s2;
#pragma unroll
    for (int j = 0; j < 4; j++) {
        if (tid == 0) { s1 = 0.0; s2 = 0.0; }
        __syncthreads();
        float v = e[j];
        float w1 = warp_sum(v), w2 = warp_sum(v * v);
        if ((tid & 31) == 0) { atomicAdd(&s1, (double)w1); atomicAdd(&s2, (double)w2); }
        __syncthreads();
        double mu = s1 / 128.0;
        double vv = s2 / 128.0 - mu * mu;
        out[tid * 4 + j] =
            (float)(((double)v - mu) * rsqrt(vv + 1e-5) * (double)ng[j] + (double)nb[j]);
        __syncthreads();
    }
}

// ---------------------------------------------------------------------------
extern "C" void kernel_launch(void* const* d_in, const int* in_sizes, int n_in,
                              void* d_out, int out_size) {
    const float* x     = (const float*)d_in[0];
    const float* w1    = (const float*)d_in[1];
    const float* b1    = (const float*)d_in[2];
    const float* bn1g  = (const float*)d_in[3];
    const float* bn1b  = (const float*)d_in[4];
    const float* w2    = (const float*)d_in[5];
    const float* b2    = (const float*)d_in[6];
    const float* bn2g  = (const float*)d_in[7];
    const float* bn2b  = (const float*)d_in[8];
    const float* theta = (const float*)d_in[9];
    const float* rho   = (const float*)d_in[10];
    const float* ng    = (const float*)d_in[11];
    const float* nbp   = (const float*)d_in[12];
    float* out = (float*)d_out;

    k_conv1<<<dim3(7, NB), 256>>>(x, w1, b1);
    k_conv2<<<dim3(14, NB), 224>>>(w2, b2, bn1g, bn1b);
    k_pool_final<<<NB, 256>>>(bn2g, bn2b, theta, rho, ng, nbp, out);
}